// round 14
// baseline (speedup 1.0000x reference)
#include <cuda_runtime.h>
#include <cuda_fp16.h>
#include <math.h>
#include <stdint.h>

// Problem constants
#define BATCH 4
#define T_SEQ 2048
#define DMODEL 1024
#define NHEADS 16
#define DHEAD 64
#define WINDOW 256
#define NTOK (BATCH * T_SEQ)          // 8192
#define QKV_F (3 * DMODEL)            // 3072
#define KDIM 1024
#define NBH (BATCH * NHEADS)          // 64

typedef __half ft;

// Scratch (device globals; allocation in kernel_launch is forbidden)
__device__ float g_qkv[(size_t)NTOK * QKV_F];
__device__ ft g_xh[(size_t)NTOK * DMODEL];
__device__ ft g_wh[(size_t)QKV_F * DMODEL];
__device__ ft g_oh[(size_t)DMODEL * DMODEL];
__device__ ft g_ol[(size_t)DMODEL * DMODEL];
__device__ ft g_ah[(size_t)NTOK * DMODEL];
// Head-major [b][h][t][d] fp16 for attention
__device__ ft g_qh[(size_t)NBH * T_SEQ * DHEAD];
__device__ ft g_kh[(size_t)NBH * T_SEQ * DHEAD];
__device__ ft g_kl[(size_t)NBH * T_SEQ * DHEAD];
__device__ ft g_vh[(size_t)NBH * T_SEQ * DHEAD];
__device__ ft g_vl[(size_t)NBH * T_SEQ * DHEAD];

// ---------------------------------------------------------------------------
// Helpers
// ---------------------------------------------------------------------------
__device__ __forceinline__ void split1(float x, ft& h, ft& l) {
    h = __float2half_rn(x);
    l = __float2half_rn(x - __half2float(h));
}
__device__ __forceinline__ uint32_t pack_f16(float a, float b) {
    uint32_t r;
    asm("cvt.rn.f16x2.f32 %0, %1, %2;" : "=r"(r) : "f"(b), "f"(a));
    return r;
}

__global__ void split_kernel(const float* __restrict__ in,
                             ft* __restrict__ hi, ft* __restrict__ lo, int n4) {
    int i = blockIdx.x * 256 + threadIdx.x;
    if (i >= n4) return;
    float4 v = ((const float4*)in)[i];
    __align__(8) ft h4[4], l4[4];
    split1(v.x, h4[0], l4[0]); split1(v.y, h4[1], l4[1]);
    split1(v.z, h4[2], l4[2]); split1(v.w, h4[3], l4[3]);
    ((uint2*)hi)[i] = *(uint2*)h4;
    ((uint2*)lo)[i] = *(uint2*)l4;
}

__global__ void conv_kernel(const float* __restrict__ in, ft* __restrict__ hi, int n4) {
    int i = blockIdx.x * 256 + threadIdx.x;
    if (i >= n4) return;
    float4 v = ((const float4*)in)[i];
    uint2 w;
    w.x = pack_f16(v.x, v.y);
    w.y = pack_f16(v.z, v.w);
    ((uint2*)hi)[i] = w;
}

__device__ __forceinline__ void cp_async16(uint32_t dst, const void* src) {
    asm volatile("cp.async.cg.shared.global [%0], [%1], 16;" :: "r"(dst), "l"(src) : "memory");
}
__device__ __forceinline__ void cp_commit() {
    asm volatile("cp.async.commit_group;" ::: "memory");
}
template <int N>
__device__ __forceinline__ void cp_wait() {
    asm volatile("cp.async.wait_group %0;" :: "n"(N) : "memory");
}

#define MMA_F16(d, a, b)                                                        \
    asm volatile("mma.sync.aligned.m16n8k16.row.col.f32.f16.f16.f32 "           \
                 "{%0,%1,%2,%3}, {%4,%5,%6,%7}, {%8,%9}, {%0,%1,%2,%3};"        \
                 : "+f"((d)[0]), "+f"((d)[1]), "+f"((d)[2]), "+f"((d)[3])       \
                 : "r"((a)[0]), "r"((a)[1]), "r"((a)[2]), "r"((a)[3]),          \
                   "r"((b)[0]), "r"((b)[1]))

#define LDSM_X4(r0, r1, r2, r3, a)                                              \
    asm volatile("ldmatrix.sync.aligned.m8n8.x4.shared.b16 {%0,%1,%2,%3}, [%4];"\
                 : "=r"(r0), "=r"(r1), "=r"(r2), "=r"(r3) : "r"(a))
#define LDSM_X4T(r0, r1, r2, r3, a)                                             \
    asm volatile("ldmatrix.sync.aligned.m8n8.x4.trans.shared.b16 {%0,%1,%2,%3}, [%4];"\
                 : "=r"(r0), "=r"(r1), "=r"(r2), "=r"(r3) : "r"(a))

// ---------------------------------------------------------------------------
// fp16 HMMA GEMM: C[M,N] = Ah[M,K] * ((Bh[+Bl])[N,K])^T, fp32 accum.
// HAS_LO selects the weight correction term. ldmatrix.x4 fragment loads
// (mapping validated in R7/R8; 80B stride is ldmatrix-conflict-free).
// Tile 128x128, BK=32, 8 warps (2x4), warp tile 64x32, 2-stage, 2 CTAs/SM.
// ---------------------------------------------------------------------------
#define ROWB 80
#define PART (128 * ROWB)
#define STAGE (3 * PART)
#define GEMM_SMEM (2 * STAGE)

template <bool HAS_LO>
__global__ __launch_bounds__(256, 2)
void gemm_hmma(const ft* __restrict__ Ah, const ft* __restrict__ Bh,
               const ft* __restrict__ Bl, float* __restrict__ C, int N) {
    extern __shared__ __align__(16) char dynsm[];
    const int tid  = threadIdx.x;
    const int warp = tid >> 5, lane = tid & 31;
    const int g = lane >> 2, tig = lane & 3;
    const int lrow = lane & 7, ltile = lane >> 3;
    const int warp_m = warp >> 2;
    const int warp_n = warp & 3;
    const int m0 = blockIdx.y * 128;
    const int n0 = blockIdx.x * 128;

    uint32_t smbase;
    asm("{ .reg .u64 t; cvta.to.shared.u64 t, %1; cvt.u32.u64 %0, t; }"
        : "=r"(smbase) : "l"(dynsm));

    const ft* Ah_ = Ah + (size_t)m0 * KDIM;
    const ft* Bh_ = Bh + (size_t)n0 * KDIM;
    const ft* Bl_ = HAS_LO ? (Bl + (size_t)n0 * KDIM) : nullptr;

    auto load_stage = [&](int c) {
        const int st = c & 1;
        const int k0 = c * 32;
        const uint32_t sb = smbase + st * STAGE;
#pragma unroll
        for (int l = 0; l < 2; ++l) {
            int idx = tid + l * 256;
            int r = idx >> 2, c8 = idx & 3;
            size_t go = (size_t)r * KDIM + k0 + c8 * 8;
            uint32_t so = (uint32_t)(r * ROWB + c8 * 16);
            cp_async16(sb + so,        Ah_ + go);
            cp_async16(sb + PART + so, Bh_ + go);
            if (HAS_LO) cp_async16(sb + 2 * PART + so, Bl_ + go);
        }
    };

    float acc[4][4][4];
#pragma unroll
    for (int i = 0; i < 4; i++)
#pragma unroll
        for (int j = 0; j < 4; j++)
#pragma unroll
            for (int v = 0; v < 4; v++) acc[i][j][v] = 0.f;

    load_stage(0);
    cp_commit();

    // ldmatrix lane address components (validated mapping)
    const uint32_t a_off = (uint32_t)((warp_m * 64 + (ltile & 1) * 8 + lrow) * ROWB + (ltile >> 1) * 16);
    const uint32_t b_off = (uint32_t)((warp_n * 32 + (ltile & 1) * 8 + lrow) * ROWB + (ltile >> 1) * 16);

    const int NC = KDIM / 32;
    for (int c = 0; c < NC; ++c) {
        if (c + 1 < NC) { load_stage(c + 1); cp_commit(); cp_wait<1>(); }
        else           { cp_wait<0>(); }
        __syncthreads();

        const uint32_t sb  = smbase + (c & 1) * STAGE;
        const uint32_t sAh = sb;
        const uint32_t sBh = sb + PART, sBl = sb + 2 * PART;

#pragma unroll
        for (int s = 0; s < 2; ++s) {
            uint32_t Afh[4][4], Bfh[4][2], Bfl[4][2];
#pragma unroll
            for (int i = 0; i < 4; ++i) {
                uint32_t ad = a_off + (uint32_t)(i * 16 * ROWB + s * 32);
                LDSM_X4(Afh[i][0], Afh[i][1], Afh[i][2], Afh[i][3], sAh + ad);
            }
#pragma unroll
            for (int jp = 0; jp < 2; ++jp) {
                uint32_t bd = b_off + (uint32_t)(jp * 16 * ROWB + s * 32);
                uint32_t h0, h1, h2, h3;
                LDSM_X4(h0, h1, h2, h3, sBh + bd);
                Bfh[2 * jp][0] = h0; Bfh[2 * jp][1] = h2;
                Bfh[2 * jp + 1][0] = h1; Bfh[2 * jp + 1][1] = h3;
                if (HAS_LO) {
                    uint32_t l0, l1, l2, l3;
                    LDSM_X4(l0, l1, l2, l3, sBl + bd);
                    Bfl[2 * jp][0] = l0; Bfl[2 * jp][1] = l2;
                    Bfl[2 * jp + 1][0] = l1; Bfl[2 * jp + 1][1] = l3;
                }
            }
#pragma unroll
            for (int i = 0; i < 4; ++i)
#pragma unroll
                for (int j = 0; j < 4; ++j)
                    MMA_F16(acc[i][j], Afh[i], Bfh[j]);
            if (HAS_LO) {
#pragma unroll
                for (int i = 0; i < 4; ++i)
#pragma unroll
                    for (int j = 0; j < 4; ++j)
                        MMA_F16(acc[i][j], Afh[i], Bfl[j]);
            }
        }
        __syncthreads();
    }

#pragma unroll
    for (int i = 0; i < 4; ++i) {
        int row = m0 + warp_m * 64 + i * 16 + g;
#pragma unroll
        for (int j = 0; j < 4; ++j) {
            int col = n0 + warp_n * 32 + j * 8 + tig * 2;
            *(float2*)&C[(size_t)row * N + col] =
                make_float2(acc[i][j][0], acc[i][j][1]);
            *(float2*)&C[(size_t)(row + 8) * N + col] =
                make_float2(acc[i][j][2], acc[i][j][3]);
        }
    }
}

// ---------------------------------------------------------------------------
// RoPE + split to head-major fp16. Q (scaled 1/8): hi only. K, V: hi+lo.
// ---------------------------------------------------------------------------
__global__ void rope_split_kernel(const float* __restrict__ qkv,
                                  const float* __restrict__ cosb,
                                  const float* __restrict__ sinb) {
    int idx = blockIdx.x * 256 + threadIdx.x;
    if (idx >= NTOK * 512) return;
    int w = idx & 511, tok = idx >> 9;
    int h = w >> 5, d = w & 31;
    int t = tok & (T_SEQ - 1), b = tok >> 11;

    const float* p = qkv + (size_t)tok * QKV_F + h * 64 + d;
    float c1 = cosb[t * 64 + d],      s1 = sinb[t * 64 + d];
    float c2 = cosb[t * 64 + d + 32], s2 = sinb[t * 64 + d + 32];
    float q1 = p[0], q2 = p[32];
    float k1 = p[1024], k2 = p[1056];
    float v1 = p[2048], v2 = p[2080];
    float qr1 = (q1 * c1 - q2 * s1) * 0.125f;
    float qr2 = (q2 * c2 + q1 * s2) * 0.125f;
    float kr1 = k1 * c1 - k2 * s1;
    float kr2 = k2 * c2 + k1 * s2;

    size_t o = ((size_t)(b * NHEADS + h) * T_SEQ + t) * 64 + d;
    ft hv, lv;
    g_qh[o]      = __float2half_rn(qr1);
    g_qh[o + 32] = __float2half_rn(qr2);
    split1(kr1, hv, lv); g_kh[o] = hv;      g_kl[o] = lv;
    split1(kr2, hv, lv); g_kh[o + 32] = hv; g_kl[o + 32] = lv;
    split1(v1,  hv, lv); g_vh[o] = hv;      g_vl[o] = lv;
    split1(v2,  hv, lv); g_vh[o + 32] = hv; g_vl[o + 32] = lv;
}

// ---------------------------------------------------------------------------
// Flash attention, fp16 x2 (R9 config — best measured). 64-query CTAs.
// ---------------------------------------------------------------------------
#define AT_ROWB 144
#define AT_PART (64 * AT_ROWB)             // 9216
#define AT_KV0  AT_PART                    // Q hi first
#define AT_STAGE (4 * AT_PART)             // Kh,Kl,Vh,Vl
#define ATTN_SMEM (AT_PART + 2 * AT_STAGE) // 82944

__global__ __launch_bounds__(128, 2)
void attn_hmma(ft* __restrict__ ah) {
    extern __shared__ __align__(16) char dynsm[];
    const int tid = threadIdx.x;
    const int warp = tid >> 5, lane = tid & 31;
    const int g = lane >> 2, tig = lane & 3;
    const int qb = blockIdx.x, h = blockIdx.y, b = blockIdx.z;
    const int q0 = qb * 64;
    const size_t headoff = (size_t)(b * NHEADS + h) * T_SEQ * 64;

    uint32_t smbase;
    asm("{ .reg .u64 t; cvta.to.shared.u64 t, %1; cvt.u32.u64 %0, t; }"
        : "=r"(smbase) : "l"(dynsm));
    const uint32_t smQh = smbase;

    auto load_q = [&]() {
#pragma unroll
        for (int l = 0; l < 4; ++l) {
            int idx = tid + l * 128;
            int r = idx >> 3, c8 = idx & 7;
            uint32_t so = (uint32_t)(r * AT_ROWB + c8 * 16);
            size_t go = headoff + (size_t)(q0 + r) * 64 + c8 * 8;
            cp_async16(smQh + so, g_qh + go);
        }
    };
    auto load_kv = [&](int kc, int st) {
        const uint32_t sb = smbase + AT_KV0 + st * AT_STAGE;
#pragma unroll
        for (int l = 0; l < 4; ++l) {
            int idx = tid + l * 128;
            int r = idx >> 3, c8 = idx & 7;
            uint32_t so = (uint32_t)(r * AT_ROWB + c8 * 16);
            size_t go = headoff + (size_t)(kc * 64 + r) * 64 + c8 * 8;
            cp_async16(sb + so,               g_kh + go);
            cp_async16(sb + AT_PART + so,     g_kl + go);
            cp_async16(sb + 2 * AT_PART + so, g_vh + go);
            cp_async16(sb + 3 * AT_PART + so, g_vl + go);
        }
    };

    const int lo = (qb >= 4) ? qb - 4 : 0;
    const int nch = qb - lo + 1;

    load_q();
    load_kv(lo, 0);
    cp_commit();
    if (nch > 1) { load_kv(lo + 1, 1); cp_commit(); }

    const int lrow = lane & 7;
    const int ltile = lane >> 3;
    const uint32_t qa_off = (uint32_t)((warp * 16 + (ltile & 1) * 8 + lrow) * AT_ROWB + (ltile >> 1) * 16);
    const uint32_t ka_row = (uint32_t)(((ltile & 1) * 8 + lrow) * AT_ROWB);
    const uint32_t va_row = (uint32_t)(((ltile & 1) * 8 + lrow) * AT_ROWB);

    uint32_t qfh[4][4];
    float o[8][4];
#pragma unroll
    for (int j = 0; j < 8; ++j)
#pragma unroll
        for (int v = 0; v < 4; ++v) o[j][v] = 0.f;
    float m0 = -1e30f, m1 = -1e30f, l0 = 0.f, l1 = 0.f;
    const int i0 = q0 + warp * 16 + g, i1 = i0 + 8;

    for (int ci = 0; ci < nch; ++ci) {
        const int kc = lo + ci;
        if (ci == nch - 1) cp_wait<0>(); else cp_wait<1>();
        __syncthreads();

        if (ci == 0) {
#pragma unroll
            for (int s = 0; s < 4; ++s)
                LDSM_X4(qfh[s][0], qfh[s][1], qfh[s][2], qfh[s][3], smQh + qa_off + s * 32);
        }

        const uint32_t sb  = smbase + AT_KV0 + (ci & 1) * AT_STAGE;
        const uint32_t sKh = sb, sKl = sb + AT_PART;
        const uint32_t sVh = sb + 2 * AT_PART, sVl = sb + 3 * AT_PART;

        float c[8][4];
#pragma unroll
        for (int j = 0; j < 8; ++j)
#pragma unroll
            for (int v = 0; v < 4; ++v) c[j][v] = 0.f;

#pragma unroll
        for (int s = 0; s < 4; ++s) {
#pragma unroll
            for (int jp = 0; jp < 4; ++jp) {
                uint32_t kh0, kh1, kh2, kh3, kl0, kl1, kl2, kl3;
                uint32_t ka = ka_row + (uint32_t)(jp * 16 * AT_ROWB) + (uint32_t)(s * 32 + (ltile >> 1) * 16);
                LDSM_X4(kh0, kh1, kh2, kh3, sKh + ka);
                LDSM_X4(kl0, kl1, kl2, kl3, sKl + ka);
                uint32_t be_h[2] = {kh0, kh2}, bo_h[2] = {kh1, kh3};
                uint32_t be_l[2] = {kl0, kl2}, bo_l[2] = {kl1, kl3};
                MMA_F16(c[2 * jp],     qfh[s], be_h);
                MMA_F16(c[2 * jp + 1], qfh[s], bo_h);
                MMA_F16(c[2 * jp],     qfh[s], be_l);
                MMA_F16(c[2 * jp + 1], qfh[s], bo_l);
            }
        }

        float rm0 = -1e30f, rm1 = -1e30f;
#pragma unroll
        for (int j = 0; j < 8; ++j) {
            int jj = kc * 64 + 8 * j + 2 * tig;
            bool ok;
            ok = (jj     <= i0) && (jj     + (WINDOW - 1) >= i0); c[j][0] = ok ? c[j][0] : -1e30f;
            ok = (jj + 1 <= i0) && (jj + 1 + (WINDOW - 1) >= i0); c[j][1] = ok ? c[j][1] : -1e30f;
            ok = (jj     <= i1) && (jj     + (WINDOW - 1) >= i1); c[j][2] = ok ? c[j][2] : -1e30f;
            ok = (jj + 1 <= i1) && (jj + 1 + (WINDOW - 1) >= i1); c[j][3] = ok ? c[j][3] : -1e30f;
            rm0 = fmaxf(rm0, fmaxf(c[j][0], c[j][1]));
            rm1 = fmaxf(rm1, fmaxf(c[j][2], c[j][3]));
        }
        rm0 = fmaxf(rm0, __shfl_xor_sync(0xffffffffu, rm0, 1));
        rm0 = fmaxf(rm0, __shfl_xor_sync(0xffffffffu, rm0, 2));
        rm1 = fmaxf(rm1, __shfl_xor_sync(0xffffffffu, rm1, 1));
        rm1 = fmaxf(rm1, __shfl_xor_sync(0xffffffffu, rm1, 2));
        float mn0 = fmaxf(m0, rm0), mn1 = fmaxf(m1, rm1);
        float cor0 = __expf(m0 - mn0), cor1 = __expf(m1 - mn1);
        float rs0 = 0.f, rs1 = 0.f;
#pragma unroll
        for (int j = 0; j < 8; ++j) {
            c[j][0] = (c[j][0] > -5e29f) ? __expf(c[j][0] - mn0) : 0.f;
            c[j][1] = (c[j][1] > -5e29f) ? __expf(c[j][1] - mn0) : 0.f;
            c[j][2] = (c[j][2] > -5e29f) ? __expf(c[j][2] - mn1) : 0.f;
            c[j][3] = (c[j][3] > -5e29f) ? __expf(c[j][3] - mn1) : 0.f;
            rs0 += c[j][0] + c[j][1];
            rs1 += c[j][2] + c[j][3];
        }
        rs0 += __shfl_xor_sync(0xffffffffu, rs0, 1);
        rs0 += __shfl_xor_sync(0xffffffffu, rs0, 2);
        rs1 += __shfl_xor_sync(0xffffffffu, rs1, 1);
        rs1 += __shfl_xor_sync(0xffffffffu, rs1, 2);
        l0 = l0 * cor0 + rs0; m0 = mn0;
        l1 = l1 * cor1 + rs1; m1 = mn1;
#pragma unroll
        for (int j = 0; j < 8; ++j) {
            o[j][0] *= cor0; o[j][1] *= cor0;
            o[j][2] *= cor1; o[j][3] *= cor1;
        }

#pragma unroll
        for (int t = 0; t < 4; ++t) {
            uint32_t pfh[4];
#pragma unroll
            for (int u = 0; u < 4; ++u) {
                float p0 = c[2 * t + (u >> 1)][(u & 1) ? 2 : 0];
                float p1 = c[2 * t + (u >> 1)][(u & 1) ? 3 : 1];
                pfh[u] = pack_f16(p0, p1);
            }
#pragma unroll
            for (int jdp = 0; jdp < 4; ++jdp) {
                uint32_t vh0, vh1, vh2, vh3, vl0, vl1, vl2, vl3;
                uint32_t va = va_row + (uint32_t)(t * 16 * AT_ROWB) + (uint32_t)(jdp * 32 + (ltile >> 1) * 16);
                LDSM_X4T(vh0, vh1, vh2, vh3, sVh + va);
                LDSM_X4T(vl0, vl1, vl2, vl3, sVl + va);
                uint32_t be_h[2] = {vh0, vh1}, bo_h[2] = {vh2, vh3};
                uint32_t be_l[2] = {vl0, vl1}, bo_l[2] = {vl2, vl3};
                MMA_F16(o[2 * jdp],     pfh, be_h);
                MMA_F16(o[2 * jdp + 1], pfh, bo_h);
                MMA_F16(o[2 * jdp],     pfh, be_l);
                MMA_F16(o[2 * jdp + 1], pfh, bo_l);
            }
        }

        __syncthreads();
        if (ci + 2 < nch) { load_kv(lo + ci + 2, ci & 1); cp_commit(); }
    }

    float inv0 = 1.f / l0, inv1 = 1.f / l1;
    const int t0 = q0 + warp * 16 + g;
#pragma unroll
    for (int jd = 0; jd < 8; ++jd) {
        int col = h * 64 + 8 * jd + 2 * tig;
        size_t idx0 = ((size_t)(b * T_SEQ + t0)) * DMODEL + col;
        size_t idx1 = ((size_t)(b * T_SEQ + t0 + 8)) * DMODEL + col;
        *(uint32_t*)&ah[idx0] = pack_f16(o[jd][0] * inv0, o[jd][1] * inv0);
        *(uint32_t*)&ah[idx1] = pack_f16(o[jd][2] * inv1, o[jd][3] * inv1);
    }
}

// ---------------------------------------------------------------------------
// Launch
// ---------------------------------------------------------------------------
extern "C" void kernel_launch(void* const* d_in, const int* in_sizes, int n_in,
                              void* d_out, int out_size) {
    const float* x     = (const float*)d_in[0];
    const float* cosb  = (const float*)d_in[1];
    const float* sinb  = (const float*)d_in[2];
    const float* qkv_w = (const float*)d_in[3];
    const float* out_w = (const float*)d_in[4];
    float* out = (float*)d_out;

    float* qkv = nullptr;
    ft *xh, *wh, *oh, *ol, *ah;
    cudaGetSymbolAddress((void**)&qkv, g_qkv);
    cudaGetSymbolAddress((void**)&xh, g_xh);
    cudaGetSymbolAddress((void**)&wh, g_wh);
    cudaGetSymbolAddress((void**)&oh, g_oh);
    cudaGetSymbolAddress((void**)&ol, g_ol);
    cudaGetSymbolAddress((void**)&ah, g_ah);

    cudaFuncSetAttribute(gemm_hmma<false>, cudaFuncAttributeMaxDynamicSharedMemorySize, GEMM_SMEM);
    cudaFuncSetAttribute(gemm_hmma<true>,  cudaFuncAttributeMaxDynamicSharedMemorySize, GEMM_SMEM);
    cudaFuncSetAttribute(attn_hmma, cudaFuncAttributeMaxDynamicSharedMemorySize, ATTN_SMEM);

    // 0) Convert x and qkv_w to fp16 (hi only); split out_w (hi+lo)
    conv_kernel<<<(NTOK * DMODEL / 4 + 255) / 256, 256>>>(x, xh, NTOK * DMODEL / 4);
    conv_kernel<<<(QKV_F * DMODEL / 4 + 255) / 256, 256>>>(qkv_w, wh, QKV_F * DMODEL / 4);
    split_kernel<<<(DMODEL * DMODEL / 4 + 255) / 256, 256>>>(out_w, oh, ol, DMODEL * DMODEL / 4);

    // 1) QKV projection (fp16 hi-only): [8192,3072] = x @ qkv_w^T
    {
        dim3 grid(QKV_F / 128, NTOK / 128);
        gemm_hmma<false><<<grid, 256, GEMM_SMEM>>>(xh, wh, nullptr, qkv, QKV_F);
    }
    // 2) RoPE + head-major fp16 split
    rope_split_kernel<<<(NTOK * 512 + 255) / 256, 256>>>(qkv, cosb, sinb);
    // 3) Flash attention (fp16 x2), 64-query CTAs, writes fp16 hi token-major
    {
        dim3 grid(T_SEQ / 64, NHEADS, BATCH);
        attn_hmma<<<grid, 128, ATTN_SMEM>>>(ah);
    }
    // 4) Output projection (fp16 x2): [8192,1024] = attn @ out_w^T
    {
        dim3 grid(DMODEL / 128, NTOK / 128);
        gemm_hmma<true><<<grid, 256, GEMM_SMEM>>>(ah, oh, ol, out, DMODEL);
    }
}

// round 15
// speedup vs baseline: 1.1137x; 1.1137x over previous
#include <cuda_runtime.h>
#include <cuda_fp16.h>
#include <math.h>
#include <stdint.h>

// Problem constants
#define BATCH 4
#define T_SEQ 2048
#define DMODEL 1024
#define NHEADS 16
#define DHEAD 64
#define WINDOW 256
#define NTOK (BATCH * T_SEQ)          // 8192
#define QKV_F (3 * DMODEL)            // 3072
#define KDIM 1024
#define NBH (BATCH * NHEADS)          // 64

typedef __half ft;

// Scratch (device globals; allocation in kernel_launch is forbidden)
__device__ float g_qkv[(size_t)NTOK * QKV_F];
__device__ ft g_xh[(size_t)NTOK * DMODEL];
__device__ ft g_wh[(size_t)QKV_F * DMODEL];
__device__ ft g_oh[(size_t)DMODEL * DMODEL];
__device__ ft g_ol[(size_t)DMODEL * DMODEL];
__device__ ft g_ah[(size_t)NTOK * DMODEL];
// Head-major [b][h][t][d] fp16 for attention
__device__ ft g_qh[(size_t)NBH * T_SEQ * DHEAD];
__device__ ft g_kh[(size_t)NBH * T_SEQ * DHEAD];
__device__ ft g_kl[(size_t)NBH * T_SEQ * DHEAD];
__device__ ft g_vh[(size_t)NBH * T_SEQ * DHEAD];
__device__ ft g_vl[(size_t)NBH * T_SEQ * DHEAD];

// ---------------------------------------------------------------------------
// Helpers
// ---------------------------------------------------------------------------
__device__ __forceinline__ void split1(float x, ft& h, ft& l) {
    h = __float2half_rn(x);
    l = __float2half_rn(x - __half2float(h));
}
__device__ __forceinline__ uint32_t pack_f16(float a, float b) {
    uint32_t r;
    asm("cvt.rn.f16x2.f32 %0, %1, %2;" : "=r"(r) : "f"(b), "f"(a));
    return r;
}

__global__ void split_kernel(const float* __restrict__ in,
                             ft* __restrict__ hi, ft* __restrict__ lo, int n4) {
    int i = blockIdx.x * 256 + threadIdx.x;
    if (i >= n4) return;
    float4 v = ((const float4*)in)[i];
    __align__(8) ft h4[4], l4[4];
    split1(v.x, h4[0], l4[0]); split1(v.y, h4[1], l4[1]);
    split1(v.z, h4[2], l4[2]); split1(v.w, h4[3], l4[3]);
    ((uint2*)hi)[i] = *(uint2*)h4;
    ((uint2*)lo)[i] = *(uint2*)l4;
}

__global__ void conv_kernel(const float* __restrict__ in, ft* __restrict__ hi, int n4) {
    int i = blockIdx.x * 256 + threadIdx.x;
    if (i >= n4) return;
    float4 v = ((const float4*)in)[i];
    uint2 w;
    w.x = pack_f16(v.x, v.y);
    w.y = pack_f16(v.z, v.w);
    ((uint2*)hi)[i] = w;
}

__device__ __forceinline__ void cp_async16(uint32_t dst, const void* src) {
    asm volatile("cp.async.cg.shared.global [%0], [%1], 16;" :: "r"(dst), "l"(src) : "memory");
}
__device__ __forceinline__ void cp_commit() {
    asm volatile("cp.async.commit_group;" ::: "memory");
}
template <int N>
__device__ __forceinline__ void cp_wait() {
    asm volatile("cp.async.wait_group %0;" :: "n"(N) : "memory");
}

#define MMA_F16(d, a, b)                                                        \
    asm volatile("mma.sync.aligned.m16n8k16.row.col.f32.f16.f16.f32 "           \
                 "{%0,%1,%2,%3}, {%4,%5,%6,%7}, {%8,%9}, {%0,%1,%2,%3};"        \
                 : "+f"((d)[0]), "+f"((d)[1]), "+f"((d)[2]), "+f"((d)[3])       \
                 : "r"((a)[0]), "r"((a)[1]), "r"((a)[2]), "r"((a)[3]),          \
                   "r"((b)[0]), "r"((b)[1]))

#define LDSM_X4(r0, r1, r2, r3, a)                                              \
    asm volatile("ldmatrix.sync.aligned.m8n8.x4.shared.b16 {%0,%1,%2,%3}, [%4];"\
                 : "=r"(r0), "=r"(r1), "=r"(r2), "=r"(r3) : "r"(a))
#define LDSM_X4T(r0, r1, r2, r3, a)                                             \
    asm volatile("ldmatrix.sync.aligned.m8n8.x4.trans.shared.b16 {%0,%1,%2,%3}, [%4];"\
                 : "=r"(r0), "=r"(r1), "=r"(r2), "=r"(r3) : "r"(a))

// ---------------------------------------------------------------------------
// fp16 HMMA GEMM: C[M,N] = Ah[M,K] * ((Bh[+Bl])[N,K])^T, fp32 accum.
// HAS_LO selects the weight correction term. Scalar-LDS fragment loads
// (fastest measured; ldmatrix regressed twice). BK=64: 144B row stride
// (128B payload + 16B pad; frag word addr (4g+tig) mod 32 -> conflict-free),
// half the barrier crossings of BK=32. Tile 128x128, 8 warps (2x4),
// warp tile 64x32, 2-stage cp.async, 2 CTAs/SM (2x110.6KB = 221KB <= 228KB).
// ---------------------------------------------------------------------------
#define ROWB 144
#define PART (128 * ROWB)            // 18432
#define STAGE (3 * PART)             // 55296
#define GEMM_SMEM (2 * STAGE)        // 110592

template <bool HAS_LO>
__global__ __launch_bounds__(256, 2)
void gemm_hmma(const ft* __restrict__ Ah, const ft* __restrict__ Bh,
               const ft* __restrict__ Bl, float* __restrict__ C, int N) {
    extern __shared__ __align__(16) char dynsm[];
    const int tid  = threadIdx.x;
    const int warp = tid >> 5, lane = tid & 31;
    const int g = lane >> 2, tig = lane & 3;
    const int warp_m = warp >> 2;
    const int warp_n = warp & 3;
    const int m0 = blockIdx.y * 128;
    const int n0 = blockIdx.x * 128;

    uint32_t smbase;
    asm("{ .reg .u64 t; cvta.to.shared.u64 t, %1; cvt.u32.u64 %0, t; }"
        : "=r"(smbase) : "l"(dynsm));

    const ft* Ah_ = Ah + (size_t)m0 * KDIM;
    const ft* Bh_ = Bh + (size_t)n0 * KDIM;
    const ft* Bl_ = HAS_LO ? (Bl + (size_t)n0 * KDIM) : nullptr;

    auto load_stage = [&](int c) {
        const int st = c & 1;
        const int k0 = c * 64;
        const uint32_t sb = smbase + st * STAGE;
#pragma unroll
        for (int l = 0; l < 4; ++l) {
            int idx = tid + l * 256;        // 0..1023: 128 rows x 8 16B-chunks
            int r = idx >> 3, c8 = idx & 7;
            size_t go = (size_t)r * KDIM + k0 + c8 * 8;
            uint32_t so = (uint32_t)(r * ROWB + c8 * 16);
            cp_async16(sb + so,        Ah_ + go);
            cp_async16(sb + PART + so, Bh_ + go);
            if (HAS_LO) cp_async16(sb + 2 * PART + so, Bl_ + go);
        }
    };

    float acc[4][4][4];
#pragma unroll
    for (int i = 0; i < 4; i++)
#pragma unroll
        for (int j = 0; j < 4; j++)
#pragma unroll
            for (int v = 0; v < 4; v++) acc[i][j][v] = 0.f;

    load_stage(0);
    cp_commit();

    const int NC = KDIM / 64;   // 16 chunks
    for (int c = 0; c < NC; ++c) {
        if (c + 1 < NC) { load_stage(c + 1); cp_commit(); cp_wait<1>(); }
        else           { cp_wait<0>(); }
        __syncthreads();

        const uint32_t sb  = smbase + (c & 1) * STAGE;
        const uint32_t sAh = sb;
        const uint32_t sBh = sb + PART, sBl = sb + 2 * PART;

#pragma unroll
        for (int s = 0; s < 4; ++s) {
            const int ksb = s * 32 + tig * 4;
            uint32_t Afh[4][4], Bfh[4][2], Bfl[4][2];
#pragma unroll
            for (int i = 0; i < 4; ++i) {
                uint32_t ro = (uint32_t)((warp_m * 64 + i * 16 + g) * ROWB + ksb);
                asm volatile("ld.shared.b32 %0, [%1];" : "=r"(Afh[i][0]) : "r"(sAh + ro));
                asm volatile("ld.shared.b32 %0, [%1];" : "=r"(Afh[i][1]) : "r"(sAh + ro + 8 * ROWB));
                asm volatile("ld.shared.b32 %0, [%1];" : "=r"(Afh[i][2]) : "r"(sAh + ro + 16));
                asm volatile("ld.shared.b32 %0, [%1];" : "=r"(Afh[i][3]) : "r"(sAh + ro + 8 * ROWB + 16));
            }
#pragma unroll
            for (int j = 0; j < 4; ++j) {
                uint32_t ro = (uint32_t)((warp_n * 32 + j * 8 + g) * ROWB + ksb);
                asm volatile("ld.shared.b32 %0, [%1];" : "=r"(Bfh[j][0]) : "r"(sBh + ro));
                asm volatile("ld.shared.b32 %0, [%1];" : "=r"(Bfh[j][1]) : "r"(sBh + ro + 16));
                if (HAS_LO) {
                    asm volatile("ld.shared.b32 %0, [%1];" : "=r"(Bfl[j][0]) : "r"(sBl + ro));
                    asm volatile("ld.shared.b32 %0, [%1];" : "=r"(Bfl[j][1]) : "r"(sBl + ro + 16));
                }
            }
#pragma unroll
            for (int i = 0; i < 4; ++i)
#pragma unroll
                for (int j = 0; j < 4; ++j)
                    MMA_F16(acc[i][j], Afh[i], Bfh[j]);
            if (HAS_LO) {
#pragma unroll
                for (int i = 0; i < 4; ++i)
#pragma unroll
                    for (int j = 0; j < 4; ++j)
                        MMA_F16(acc[i][j], Afh[i], Bfl[j]);
            }
        }
        __syncthreads();
    }

#pragma unroll
    for (int i = 0; i < 4; ++i) {
        int row = m0 + warp_m * 64 + i * 16 + g;
#pragma unroll
        for (int j = 0; j < 4; ++j) {
            int col = n0 + warp_n * 32 + j * 8 + tig * 2;
            *(float2*)&C[(size_t)row * N + col] =
                make_float2(acc[i][j][0], acc[i][j][1]);
            *(float2*)&C[(size_t)(row + 8) * N + col] =
                make_float2(acc[i][j][2], acc[i][j][3]);
        }
    }
}

// ---------------------------------------------------------------------------
// RoPE + split to head-major fp16. Q (scaled 1/8): hi only. K, V: hi+lo.
// ---------------------------------------------------------------------------
__global__ void rope_split_kernel(const float* __restrict__ qkv,
                                  const float* __restrict__ cosb,
                                  const float* __restrict__ sinb) {
    int idx = blockIdx.x * 256 + threadIdx.x;
    if (idx >= NTOK * 512) return;
    int w = idx & 511, tok = idx >> 9;
    int h = w >> 5, d = w & 31;
    int t = tok & (T_SEQ - 1), b = tok >> 11;

    const float* p = qkv + (size_t)tok * QKV_F + h * 64 + d;
    float c1 = cosb[t * 64 + d],      s1 = sinb[t * 64 + d];
    float c2 = cosb[t * 64 + d + 32], s2 = sinb[t * 64 + d + 32];
    float q1 = p[0], q2 = p[32];
    float k1 = p[1024], k2 = p[1056];
    float v1 = p[2048], v2 = p[2080];
    float qr1 = (q1 * c1 - q2 * s1) * 0.125f;
    float qr2 = (q2 * c2 + q1 * s2) * 0.125f;
    float kr1 = k1 * c1 - k2 * s1;
    float kr2 = k2 * c2 + k1 * s2;

    size_t o = ((size_t)(b * NHEADS + h) * T_SEQ + t) * 64 + d;
    ft hv, lv;
    g_qh[o]      = __float2half_rn(qr1);
    g_qh[o + 32] = __float2half_rn(qr2);
    split1(kr1, hv, lv); g_kh[o] = hv;      g_kl[o] = lv;
    split1(kr2, hv, lv); g_kh[o + 32] = hv; g_kl[o + 32] = lv;
    split1(v1,  hv, lv); g_vh[o] = hv;      g_vl[o] = lv;
    split1(v2,  hv, lv); g_vh[o + 32] = hv; g_vl[o + 32] = lv;
}

// ---------------------------------------------------------------------------
// Flash attention, fp16 x2 (R9 config — best measured). 64-query CTAs.
// ---------------------------------------------------------------------------
#define AT_ROWB 144
#define AT_PART (64 * AT_ROWB)             // 9216
#define AT_KV0  AT_PART                    // Q hi first
#define AT_STAGE (4 * AT_PART)             // Kh,Kl,Vh,Vl
#define ATTN_SMEM (AT_PART + 2 * AT_STAGE) // 82944

__global__ __launch_bounds__(128, 2)
void attn_hmma(ft* __restrict__ ah) {
    extern __shared__ __align__(16) char dynsm[];
    const int tid = threadIdx.x;
    const int warp = tid >> 5, lane = tid & 31;
    const int g = lane >> 2, tig = lane & 3;
    const int qb = blockIdx.x, h = blockIdx.y, b = blockIdx.z;
    const int q0 = qb * 64;
    const size_t headoff = (size_t)(b * NHEADS + h) * T_SEQ * 64;

    uint32_t smbase;
    asm("{ .reg .u64 t; cvta.to.shared.u64 t, %1; cvt.u32.u64 %0, t; }"
        : "=r"(smbase) : "l"(dynsm));
    const uint32_t smQh = smbase;

    auto load_q = [&]() {
#pragma unroll
        for (int l = 0; l < 4; ++l) {
            int idx = tid + l * 128;
            int r = idx >> 3, c8 = idx & 7;
            uint32_t so = (uint32_t)(r * AT_ROWB + c8 * 16);
            size_t go = headoff + (size_t)(q0 + r) * 64 + c8 * 8;
            cp_async16(smQh + so, g_qh + go);
        }
    };
    auto load_kv = [&](int kc, int st) {
        const uint32_t sb = smbase + AT_KV0 + st * AT_STAGE;
#pragma unroll
        for (int l = 0; l < 4; ++l) {
            int idx = tid + l * 128;
            int r = idx >> 3, c8 = idx & 7;
            uint32_t so = (uint32_t)(r * AT_ROWB + c8 * 16);
            size_t go = headoff + (size_t)(kc * 64 + r) * 64 + c8 * 8;
            cp_async16(sb + so,               g_kh + go);
            cp_async16(sb + AT_PART + so,     g_kl + go);
            cp_async16(sb + 2 * AT_PART + so, g_vh + go);
            cp_async16(sb + 3 * AT_PART + so, g_vl + go);
        }
    };

    const int lo = (qb >= 4) ? qb - 4 : 0;
    const int nch = qb - lo + 1;

    load_q();
    load_kv(lo, 0);
    cp_commit();
    if (nch > 1) { load_kv(lo + 1, 1); cp_commit(); }

    const int lrow = lane & 7;
    const int ltile = lane >> 3;
    const uint32_t qa_off = (uint32_t)((warp * 16 + (ltile & 1) * 8 + lrow) * AT_ROWB + (ltile >> 1) * 16);
    const uint32_t ka_row = (uint32_t)(((ltile & 1) * 8 + lrow) * AT_ROWB);
    const uint32_t va_row = (uint32_t)(((ltile & 1) * 8 + lrow) * AT_ROWB);

    uint32_t qfh[4][4];
    float o[8][4];
#pragma unroll
    for (int j = 0; j < 8; ++j)
#pragma unroll
        for (int v = 0; v < 4; ++v) o[j][v] = 0.f;
    float m0 = -1e30f, m1 = -1e30f, l0 = 0.f, l1 = 0.f;
    const int i0 = q0 + warp * 16 + g, i1 = i0 + 8;

    for (int ci = 0; ci < nch; ++ci) {
        const int kc = lo + ci;
        if (ci == nch - 1) cp_wait<0>(); else cp_wait<1>();
        __syncthreads();

        if (ci == 0) {
#pragma unroll
            for (int s = 0; s < 4; ++s)
                LDSM_X4(qfh[s][0], qfh[s][1], qfh[s][2], qfh[s][3], smQh + qa_off + s * 32);
        }

        const uint32_t sb  = smbase + AT_KV0 + (ci & 1) * AT_STAGE;
        const uint32_t sKh = sb, sKl = sb + AT_PART;
        const uint32_t sVh = sb + 2 * AT_PART, sVl = sb + 3 * AT_PART;

        float c[8][4];
#pragma unroll
        for (int j = 0; j < 8; ++j)
#pragma unroll
            for (int v = 0; v < 4; ++v) c[j][v] = 0.f;

#pragma unroll
        for (int s = 0; s < 4; ++s) {
#pragma unroll
            for (int jp = 0; jp < 4; ++jp) {
                uint32_t kh0, kh1, kh2, kh3, kl0, kl1, kl2, kl3;
                uint32_t ka = ka_row + (uint32_t)(jp * 16 * AT_ROWB) + (uint32_t)(s * 32 + (ltile >> 1) * 16);
                LDSM_X4(kh0, kh1, kh2, kh3, sKh + ka);
                LDSM_X4(kl0, kl1, kl2, kl3, sKl + ka);
                uint32_t be_h[2] = {kh0, kh2}, bo_h[2] = {kh1, kh3};
                uint32_t be_l[2] = {kl0, kl2}, bo_l[2] = {kl1, kl3};
                MMA_F16(c[2 * jp],     qfh[s], be_h);
                MMA_F16(c[2 * jp + 1], qfh[s], bo_h);
                MMA_F16(c[2 * jp],     qfh[s], be_l);
                MMA_F16(c[2 * jp + 1], qfh[s], bo_l);
            }
        }

        float rm0 = -1e30f, rm1 = -1e30f;
#pragma unroll
        for (int j = 0; j < 8; ++j) {
            int jj = kc * 64 + 8 * j + 2 * tig;
            bool ok;
            ok = (jj     <= i0) && (jj     + (WINDOW - 1) >= i0); c[j][0] = ok ? c[j][0] : -1e30f;
            ok = (jj + 1 <= i0) && (jj + 1 + (WINDOW - 1) >= i0); c[j][1] = ok ? c[j][1] : -1e30f;
            ok = (jj     <= i1) && (jj     + (WINDOW - 1) >= i1); c[j][2] = ok ? c[j][2] : -1e30f;
            ok = (jj + 1 <= i1) && (jj + 1 + (WINDOW - 1) >= i1); c[j][3] = ok ? c[j][3] : -1e30f;
            rm0 = fmaxf(rm0, fmaxf(c[j][0], c[j][1]));
            rm1 = fmaxf(rm1, fmaxf(c[j][2], c[j][3]));
        }
        rm0 = fmaxf(rm0, __shfl_xor_sync(0xffffffffu, rm0, 1));
        rm0 = fmaxf(rm0, __shfl_xor_sync(0xffffffffu, rm0, 2));
        rm1 = fmaxf(rm1, __shfl_xor_sync(0xffffffffu, rm1, 1));
        rm1 = fmaxf(rm1, __shfl_xor_sync(0xffffffffu, rm1, 2));
        float mn0 = fmaxf(m0, rm0), mn1 = fmaxf(m1, rm1);
        float cor0 = __expf(m0 - mn0), cor1 = __expf(m1 - mn1);
        float rs0 = 0.f, rs1 = 0.f;
#pragma unroll
        for (int j = 0; j < 8; ++j) {
            c[j][0] = (c[j][0] > -5e29f) ? __expf(c[j][0] - mn0) : 0.f;
            c[j][1] = (c[j][1] > -5e29f) ? __expf(c[j][1] - mn0) : 0.f;
            c[j][2] = (c[j][2] > -5e29f) ? __expf(c[j][2] - mn1) : 0.f;
            c[j][3] = (c[j][3] > -5e29f) ? __expf(c[j][3] - mn1) : 0.f;
            rs0 += c[j][0] + c[j][1];
            rs1 += c[j][2] + c[j][3];
        }
        rs0 += __shfl_xor_sync(0xffffffffu, rs0, 1);
        rs0 += __shfl_xor_sync(0xffffffffu, rs0, 2);
        rs1 += __shfl_xor_sync(0xffffffffu, rs1, 1);
        rs1 += __shfl_xor_sync(0xffffffffu, rs1, 2);
        l0 = l0 * cor0 + rs0; m0 = mn0;
        l1 = l1 * cor1 + rs1; m1 = mn1;
#pragma unroll
        for (int j = 0; j < 8; ++j) {
            o[j][0] *= cor0; o[j][1] *= cor0;
            o[j][2] *= cor1; o[j][3] *= cor1;
        }

#pragma unroll
        for (int t = 0; t < 4; ++t) {
            uint32_t pfh[4];
#pragma unroll
            for (int u = 0; u < 4; ++u) {
                float p0 = c[2 * t + (u >> 1)][(u & 1) ? 2 : 0];
                float p1 = c[2 * t + (u >> 1)][(u & 1) ? 3 : 1];
                pfh[u] = pack_f16(p0, p1);
            }
#pragma unroll
            for (int jdp = 0; jdp < 4; ++jdp) {
                uint32_t vh0, vh1, vh2, vh3, vl0, vl1, vl2, vl3;
                uint32_t va = va_row + (uint32_t)(t * 16 * AT_ROWB) + (uint32_t)(jdp * 32 + (ltile >> 1) * 16);
                LDSM_X4T(vh0, vh1, vh2, vh3, sVh + va);
                LDSM_X4T(vl0, vl1, vl2, vl3, sVl + va);
                uint32_t be_h[2] = {vh0, vh1}, bo_h[2] = {vh2, vh3};
                uint32_t be_l[2] = {vl0, vl1}, bo_l[2] = {vl2, vl3};
                MMA_F16(o[2 * jdp],     pfh, be_h);
                MMA_F16(o[2 * jdp + 1], pfh, bo_h);
                MMA_F16(o[2 * jdp],     pfh, be_l);
                MMA_F16(o[2 * jdp + 1], pfh, bo_l);
            }
        }

        __syncthreads();
        if (ci + 2 < nch) { load_kv(lo + ci + 2, ci & 1); cp_commit(); }
    }

    float inv0 = 1.f / l0, inv1 = 1.f / l1;
    const int t0 = q0 + warp * 16 + g;
#pragma unroll
    for (int jd = 0; jd < 8; ++jd) {
        int col = h * 64 + 8 * jd + 2 * tig;
        size_t idx0 = ((size_t)(b * T_SEQ + t0)) * DMODEL + col;
        size_t idx1 = ((size_t)(b * T_SEQ + t0 + 8)) * DMODEL + col;
        *(uint32_t*)&ah[idx0] = pack_f16(o[jd][0] * inv0, o[jd][1] * inv0);
        *(uint32_t*)&ah[idx1] = pack_f16(o[jd][2] * inv1, o[jd][3] * inv1);
    }
}

// ---------------------------------------------------------------------------
// Launch
// ---------------------------------------------------------------------------
extern "C" void kernel_launch(void* const* d_in, const int* in_sizes, int n_in,
                              void* d_out, int out_size) {
    const float* x     = (const float*)d_in[0];
    const float* cosb  = (const float*)d_in[1];
    const float* sinb  = (const float*)d_in[2];
    const float* qkv_w = (const float*)d_in[3];
    const float* out_w = (const float*)d_in[4];
    float* out = (float*)d_out;

    float* qkv = nullptr;
    ft *xh, *wh, *oh, *ol, *ah;
    cudaGetSymbolAddress((void**)&qkv, g_qkv);
    cudaGetSymbolAddress((void**)&xh, g_xh);
    cudaGetSymbolAddress((void**)&wh, g_wh);
    cudaGetSymbolAddress((void**)&oh, g_oh);
    cudaGetSymbolAddress((void**)&ol, g_ol);
    cudaGetSymbolAddress((void**)&ah, g_ah);

    cudaFuncSetAttribute(gemm_hmma<false>, cudaFuncAttributeMaxDynamicSharedMemorySize, GEMM_SMEM);
    cudaFuncSetAttribute(gemm_hmma<true>,  cudaFuncAttributeMaxDynamicSharedMemorySize, GEMM_SMEM);
    cudaFuncSetAttribute(attn_hmma, cudaFuncAttributeMaxDynamicSharedMemorySize, ATTN_SMEM);

    // 0) Convert x and qkv_w to fp16 (hi only); split out_w (hi+lo)
    conv_kernel<<<(NTOK * DMODEL / 4 + 255) / 256, 256>>>(x, xh, NTOK * DMODEL / 4);
    conv_kernel<<<(QKV_F * DMODEL / 4 + 255) / 256, 256>>>(qkv_w, wh, QKV_F * DMODEL / 4);
    split_kernel<<<(DMODEL * DMODEL / 4 + 255) / 256, 256>>>(out_w, oh, ol, DMODEL * DMODEL / 4);

    // 1) QKV projection (fp16 hi-only): [8192,3072] = x @ qkv_w^T
    {
        dim3 grid(QKV_F / 128, NTOK / 128);
        gemm_hmma<false><<<grid, 256, GEMM_SMEM>>>(xh, wh, nullptr, qkv, QKV_F);
    }
    // 2) RoPE + head-major fp16 split
    rope_split_kernel<<<(NTOK * 512 + 255) / 256, 256>>>(qkv, cosb, sinb);
    // 3) Flash attention (fp16 x2), 64-query CTAs, writes fp16 hi token-major
    {
        dim3 grid(T_SEQ / 64, NHEADS, BATCH);
        attn_hmma<<<grid, 128, ATTN_SMEM>>>(ah);
    }
    // 4) Output projection (fp16 x2): [8192,1024] = attn @ out_w^T
    {
        dim3 grid(DMODEL / 128, NTOK / 128);
        gemm_hmma<true><<<grid, 256, GEMM_SMEM>>>(ah, oh, ol, out, DMODEL);
    }
}